// round 16
// baseline (speedup 1.0000x reference)
#include <cuda_runtime.h>
#include <cuda_bf16.h>
#include <cstdint>

// Problem constants
#define M_ROWS 4096
#define K_DIM  256
#define NN     16384
#define KTOP   1638
#define KE     768                  // 3 x 256 (bf16 hi/lo split expansion)
#define NKT    48                   // KE/16 k16-tiles
#define SLOTS  64                   // CSC capacity per column (max nnz ~48)

// ---------------------------------------------------------------------------
// Scratch
//   g_A: A operand in m16n8k16 A-fragment order: [mtile(256)][kt(48)][lane]x uint4
//   g_B: B operand in B-fragment order: [ntile(2048)][kt(48)][lane] x uint2
//   g_pairT/g_cnt: exact-fp32 CSC of W for the top-K boundary fixup.
// ---------------------------------------------------------------------------
__device__ uint4  g_A[(size_t)256 * NKT * 32];          // 6.3 MB
__device__ uint2  g_B[(size_t)2048 * NKT * 32];         // 25.2 MB
__device__ float2 g_pairT[(size_t)SLOTS * NN];          // 8.4 MB
__device__ int    g_cnt[NN];

__device__ __forceinline__ uint32_t pk_bf16(float a, float b) {
    return (uint32_t)__bfloat16_as_ushort(__float2bfloat16(a))
         | ((uint32_t)__bfloat16_as_ushort(__float2bfloat16(b)) << 16);
}
__device__ __forceinline__ float lo_part(float v) {
    return v - __bfloat162float(__float2bfloat16(v));
}
__device__ __forceinline__ uint32_t smem_u32(const void* p) {
    uint32_t a;
    asm("{ .reg .u64 t; cvta.to.shared.u64 t, %1; cvt.u32.u64 %0, t; }" : "=r"(a) : "l"(p));
    return a;
}
#define CP_ASYNC16(dst, src) \
    asm volatile("cp.async.ca.shared.global [%0], [%1], 16;\n" :: "r"(dst), "l"(src))
#define CP_COMMIT() asm volatile("cp.async.commit_group;\n")
#define CP_WAIT1()  asm volatile("cp.async.wait_group 1;\n" ::: "memory")

// ---------------------------------------------------------------------------
// Kernel: build exact CSC (for fixup). Coalesced over n.
// ---------------------------------------------------------------------------
__global__ void __launch_bounds__(128) build_pack_kernel(const float* __restrict__ W) {
    const int n = blockIdx.x * blockDim.x + threadIdx.x;
    if (n >= NN) return;
    int c = 0;
    for (int k = 0; k < K_DIM; ++k) {
        const float w = W[(size_t)k * NN + n];
        if (w != 0.0f) {
            if (c < SLOTS) g_pairT[(size_t)c * NN + n] = make_float2(w, __int_as_float(k));
            ++c;
        }
    }
    g_cnt[n] = (c < SLOTS) ? c : SLOTS;
}

// ---------------------------------------------------------------------------
// Kernel: prep A' (x split hi|lo|hi) directly into A-fragment order.
// ---------------------------------------------------------------------------
__global__ void __launch_bounds__(256) prep_a_kernel(const float* __restrict__ x) {
    const int id = blockIdx.x * 256 + threadIdx.x;      // < 256*48*32
    const int mtile = id / (NKT * 32);
    const int kt    = (id % (NKT * 32)) >> 5;
    const int lane  = id & 31;
    const int g = lane >> 2, t = lane & 3;
    const int s = kt / 16;                              // split 0,1,2
    const int kb = (kt % 16) * 16 + t * 2;
    const int r0 = mtile * 16 + g, r1 = r0 + 8;

    const float v00 = x[(size_t)r0 * K_DIM + kb + 0];
    const float v01 = x[(size_t)r0 * K_DIM + kb + 1];
    const float v10 = x[(size_t)r1 * K_DIM + kb + 0];
    const float v11 = x[(size_t)r1 * K_DIM + kb + 1];
    const float v02 = x[(size_t)r0 * K_DIM + kb + 8];
    const float v03 = x[(size_t)r0 * K_DIM + kb + 9];
    const float v12 = x[(size_t)r1 * K_DIM + kb + 8];
    const float v13 = x[(size_t)r1 * K_DIM + kb + 9];

    const float a00 = (s == 1) ? lo_part(v00) : v00;
    const float a01 = (s == 1) ? lo_part(v01) : v01;
    const float a10 = (s == 1) ? lo_part(v10) : v10;
    const float a11 = (s == 1) ? lo_part(v11) : v11;
    const float a02 = (s == 1) ? lo_part(v02) : v02;
    const float a03 = (s == 1) ? lo_part(v03) : v03;
    const float a12 = (s == 1) ? lo_part(v12) : v12;
    const float a13 = (s == 1) ? lo_part(v13) : v13;

    g_A[id] = make_uint4(pk_bf16(a00, a01), pk_bf16(a10, a11),
                         pk_bf16(a02, a03), pk_bf16(a12, a13));
}

// ---------------------------------------------------------------------------
// Kernel: prep B' (W^T split hi|hi|lo) into B-fragment order via 64x64
// smem transpose tile (coalesced W reads).
// ---------------------------------------------------------------------------
__global__ void __launch_bounds__(256) prep_b_kernel(const float* __restrict__ W) {
    __shared__ float tw[64][65];
    const int n0 = blockIdx.x * 64;
    const int k0 = blockIdx.y * 64;
    const int tid = threadIdx.x;

    for (int u = tid; u < 64 * 64; u += 256) {
        const int kk = u >> 6, nn = u & 63;
        tw[kk][nn] = W[(size_t)(k0 + kk) * NN + n0 + nn];
    }
    __syncthreads();

    for (int u = tid; u < 8 * 4 * 32; u += 256) {
        const int nt  = u >> 7;
        const int ktl = (u >> 5) & 3;
        const int ln  = u & 31;
        const int g = ln >> 2, t = ln & 3;
        const int nn = nt * 8 + g;
        const int kb = ktl * 16 + t * 2;
        const float w0 = tw[kb + 0][nn];
        const float w1 = tw[kb + 1][nn];
        const float w2 = tw[kb + 8][nn];
        const float w3 = tw[kb + 9][nn];
        const int ntile = (n0 >> 3) + nt;
#pragma unroll
        for (int s = 0; s < 3; ++s) {
            const int ktg = s * 16 + (k0 >> 4) + ktl;
            const float b0 = (s == 2) ? lo_part(w0) : w0;
            const float b1 = (s == 2) ? lo_part(w1) : w1;
            const float b2 = (s == 2) ? lo_part(w2) : w2;
            const float b3 = (s == 2) ? lo_part(w3) : w3;
            g_B[((size_t)ntile * NKT + ktg) * 32 + ln] =
                make_uint2(pk_bf16(b0, b1), pk_bf16(b2, b3));
        }
    }
}

// ---------------------------------------------------------------------------
// Kernel: tensor-core GEMM  out = relu(A' @ B'^T + bias)  (h~, err ~1.5e-6)
// CTA tile 128x256, 256 threads / 8 warps (2m x 4n), warp tile 64x64
// (i=4 m-frags, j=8 n-frags -> 1.0 L1-wavefront/MMA vs 1.5 in R15).
// K=768 in 12 chunks of 64; 3-stage cp.async pipeline (48KB/stage).
// ---------------------------------------------------------------------------
#define GT 256
#define STAGE_B 49152                 // A 16KB + B 32KB
#define GSMEM (3 * STAGE_B)           // 144KB -> 1 CTA/SM
#define OS_STRIDE 129

__global__ void __launch_bounds__(GT) gemm_mma_kernel(
    const float* __restrict__ bias, float* __restrict__ out)
{
    extern __shared__ char smem[];
    const uint32_t sbase = smem_u32(smem);
    const int tid  = threadIdx.x;
    const int warp = tid >> 5, lane = tid & 31;
    const int wm = warp >> 2, wn = warp & 3;            // 2 x 4
    const int nb = blockIdx.x, mb = blockIdx.y;
    const int row0 = mb * 128, col0 = nb * 256;

    float acc[4][8][4];
#pragma unroll
    for (int i = 0; i < 4; ++i)
#pragma unroll
        for (int j = 0; j < 8; ++j)
#pragma unroll
            for (int q = 0; q < 4; ++q) acc[i][j][q] = 0.f;

    const uint4* gA4 = g_A;
    const uint4* gB4 = (const uint4*)g_B;

    // async-copy chunk c into stage p. A: 1024 uint4; B: 2048 uint4.
    auto issue_copy = [&](int c, int p) {
        const uint32_t abase = sbase + p * STAGE_B;
        const uint32_t bbase = abase + 16384;
#pragma unroll
        for (int u4 = 0; u4 < 4; ++u4) {
            const int u = tid + u4 * GT;                 // 0..1023
            const uint4* srcA = gA4 + ((size_t)(mb * 8 + (u >> 7)) * NKT + c * 4) * 32 + (u & 127);
            CP_ASYNC16(abase + u * 16, srcA);
        }
#pragma unroll
        for (int u4 = 0; u4 < 8; ++u4) {
            const int u = tid + u4 * GT;                 // 0..2047
            const uint4* srcB = gB4 + ((size_t)(nb * 32 + (u >> 6)) * NKT + c * 4) * 16 + (u & 63);
            CP_ASYNC16(bbase + u * 16, srcB);
        }
        CP_COMMIT();
    };

    issue_copy(0, 0);
    issue_copy(1, 1);

    for (int c = 0; c < 12; ++c) {
        CP_WAIT1();
        __syncthreads();
        if (c + 2 < 12) issue_copy(c + 2, (c + 2) % 3);
        else CP_COMMIT();

        const int p = c % 3;
        const uint4* a = (const uint4*)(smem + p * STAGE_B);
        const uint2* b = (const uint2*)(smem + p * STAGE_B + 16384);
#pragma unroll
        for (int kt4 = 0; kt4 < 4; ++kt4) {
            uint4 af[4]; uint2 bf[8];
#pragma unroll
            for (int i = 0; i < 4; ++i)
                af[i] = a[((wm * 4 + i) * 4 + kt4) * 32 + lane];
#pragma unroll
            for (int j = 0; j < 8; ++j)
                bf[j] = b[((wn * 8 + j) * 4 + kt4) * 32 + lane];
#pragma unroll
            for (int i = 0; i < 4; ++i)
#pragma unroll
                for (int j = 0; j < 8; ++j) {
                    asm volatile(
                        "mma.sync.aligned.m16n8k16.row.col.f32.bf16.bf16.f32 "
                        "{%0,%1,%2,%3}, {%4,%5,%6,%7}, {%8,%9}, {%0,%1,%2,%3};\n"
                        : "+f"(acc[i][j][0]), "+f"(acc[i][j][1]),
                          "+f"(acc[i][j][2]), "+f"(acc[i][j][3])
                        : "r"(af[i].x), "r"(af[i].y), "r"(af[i].z), "r"(af[i].w),
                          "r"(bf[j].x), "r"(bf[j].y));
                }
        }
    }
    __syncthreads();                                     // smem free for epilogue

    // epilogue: two 128-col half passes through smem, coalesced float4 flush
    float* os = (float*)smem;                            // [128][129]
    const int g = lane >> 2, t = lane & 3;
    for (int half = 0; half < 2; ++half) {
        if ((wn >> 1) == half) {
#pragma unroll
            for (int i = 0; i < 4; ++i)
#pragma unroll
                for (int j = 0; j < 8; ++j) {
                    const int rl = (wm * 4 + i) * 16 + g;
                    const int cl = (wn & 1) * 64 + j * 8 + t * 2;
                    const int cg = col0 + half * 128 + cl;
                    const float b0 = __ldg(bias + cg), b1 = __ldg(bias + cg + 1);
                    os[(rl + 0) * OS_STRIDE + cl + 0] = fmaxf(acc[i][j][0] + b0, 0.f);
                    os[(rl + 0) * OS_STRIDE + cl + 1] = fmaxf(acc[i][j][1] + b1, 0.f);
                    os[(rl + 8) * OS_STRIDE + cl + 0] = fmaxf(acc[i][j][2] + b0, 0.f);
                    os[(rl + 8) * OS_STRIDE + cl + 1] = fmaxf(acc[i][j][3] + b1, 0.f);
                }
        }
        __syncthreads();
        for (int l = tid; l < 128 * 32; l += GT) {
            const int r = l >> 5, c4 = (l & 31) * 4;
            float4 v;
            v.x = os[r * OS_STRIDE + c4 + 0];
            v.y = os[r * OS_STRIDE + c4 + 1];
            v.z = os[r * OS_STRIDE + c4 + 2];
            v.w = os[r * OS_STRIDE + c4 + 3];
            *(float4*)(out + (size_t)(row0 + r) * NN + col0 + half * 128 + c4) = v;
        }
        __syncthreads();
    }
}

// ---------------------------------------------------------------------------
// Kernel: top-K with EXACT boundary fixup. 2 full-row reads + 1 write:
// pass1 = 12-bit histogram; pass2 = fused compact + masked write-back;
// then exact recompute/rank of threshold-bin candidates + scatter.
// ---------------------------------------------------------------------------
#define CAP 2048

__global__ void __launch_bounds__(256) topk_kernel(
    float* __restrict__ out, const float* __restrict__ x,
    const float* __restrict__ bias)
{
    __shared__ int hist[4096];
    __shared__ unsigned int candv[CAP];
    __shared__ int candi[CAP];
    __shared__ int keepf[CAP];
    __shared__ float xrow[K_DIM];
    __shared__ int chunksum[256];
    __shared__ int s_b1, s_krem, s_cnt;

    const int t = threadIdx.x;
    const int lane = t & 31;
    const int row = blockIdx.x;
    float* rp = out + (size_t)row * NN;
    const uint4* rp4 = (const uint4*)rp;

    xrow[t] = x[(size_t)row * K_DIM + t];
    for (int i = t; i < 4096; i += 256) hist[i] = 0;
    if (t == 0) s_cnt = 0;
    __syncthreads();

    // ---- pass 1: 12-bit histogram of h~ bits ----
    {
        int zc = 0;
        for (int i = t; i < NN / 4; i += 256) {
            const uint4 q = rp4[i];
            if (q.x) atomicAdd(&hist[q.x >> 20], 1); else ++zc;
            if (q.y) atomicAdd(&hist[q.y >> 20], 1); else ++zc;
            if (q.z) atomicAdd(&hist[q.z >> 20], 1); else ++zc;
            if (q.w) atomicAdd(&hist[q.w >> 20], 1); else ++zc;
        }
#pragma unroll
        for (int off = 16; off; off >>= 1) zc += __shfl_down_sync(0xffffffffu, zc, off);
        if (lane == 0 && zc) atomicAdd(&hist[0], zc);
    }
    __syncthreads();
    { int s = 0; for (int k = 0; k < 16; ++k) s += hist[t * 16 + k]; chunksum[t] = s; }
    __syncthreads();
    if (t == 0) {
        int kr = KTOP, c = 255;
        for (;; --c) { const int h = chunksum[c]; if (h >= kr) break; kr -= h; }
        int b = c * 16 + 15;
        for (;; --b) { const int h = hist[b]; if (h >= kr) break; kr -= h; }
        s_b1 = b; s_krem = kr;
    }
    __syncthreads();
    const int b1 = s_b1;
    const int krem = s_krem;

    if (b1 == 0) return;   // threshold in zero/denormal bin: keep everything

    // ---- pass 2 (fused): compact threshold-bin candidates + write mask ----
    uint4* wp4 = (uint4*)rp;
    for (int i = t; i < NN / 4; i += 256) {
        uint4 q = rp4[i];
        const int base = i * 4;
        unsigned int* pc = (unsigned int*)&q;
#pragma unroll
        for (int c2 = 0; c2 < 4; ++c2) {
            const int bin = (int)(pc[c2] >> 20);
            if (bin == b1) {
                const int p = atomicAdd(&s_cnt, 1);
                if (p < CAP) { candv[p] = pc[c2]; candi[p] = base + c2; }
                pc[c2] = 0u;                 // zero now; scatter fixes keeps
            } else if (bin < b1) {
                pc[c2] = 0u;
            }
        }
        wp4[i] = q;
    }
    __syncthreads();
    const int cnt = (s_cnt < CAP) ? s_cnt : CAP;   // clamp (cnt>CAP ~impossible)

    // ---- exact recompute of candidates (k-ascending fmaf, ref-matched) ----
    for (int i = t; i < cnt; i += 256) {
        const int n = candi[i];
        const int cn = g_cnt[n];
        float sum = 0.f;
        for (int s = 0; s < cn; ++s) {
            const float2 p = g_pairT[(size_t)s * NN + n];
            sum = fmaf(xrow[__float_as_int(p.y)], p.x, sum);
        }
        const float h = fmaxf(sum + __ldg(bias + n), 0.f);
        candv[i] = __float_as_uint(h);
    }
    __syncthreads();

    // ---- exact ranking among candidates, lowest-index ties first ----
    for (int i = t; i < cnt; i += 256) {
        const unsigned int u = candv[i];
        const int idx = candi[i];
        int r = 0;
        for (int j = 0; j < cnt; ++j) {
            const unsigned int v = candv[j];
            r += (v > u) || (v == u && candi[j] < idx);
        }
        keepf[i] = (r < krem);
    }
    __syncthreads();

    // ---- scatter kept candidates with EXACT values ----
    for (int i = t; i < cnt; i += 256)
        if (keepf[i]) rp[candi[i]] = __uint_as_float(candv[i]);
}

// ---------------------------------------------------------------------------
// Launch
// ---------------------------------------------------------------------------
extern "C" void kernel_launch(void* const* d_in, const int* in_sizes, int n_in,
                              void* d_out, int out_size)
{
    const float* x = nullptr;
    const float* W = nullptr;
    const float* bias = nullptr;
    for (int i = 0; i < n_in; ++i) {
        if (in_sizes[i] == M_ROWS * K_DIM)      x = (const float*)d_in[i];
        else if (in_sizes[i] == K_DIM * NN)     W = (const float*)d_in[i];
        else if (in_sizes[i] == NN)             bias = (const float*)d_in[i];
    }
    float* out = (float*)d_out;

    cudaFuncSetAttribute(gemm_mma_kernel, cudaFuncAttributeMaxDynamicSharedMemorySize, GSMEM);

    build_pack_kernel<<<NN / 128, 128>>>(W);
    prep_a_kernel<<<(256 * NKT * 32) / 256, 256>>>(x);
    {
        dim3 g(NN / 64, K_DIM / 64);     // 256 x 4
        prep_b_kernel<<<g, 256>>>(W);
    }

    dim3 ggrid(NN / 256, M_ROWS / 128);  // 64 x 32
    gemm_mma_kernel<<<ggrid, GT, GSMEM>>>(bias, out);

    topk_kernel<<<M_ROWS, 256>>>(out, x, bias);
}

// round 17
// speedup vs baseline: 1.1561x; 1.1561x over previous
#include <cuda_runtime.h>
#include <cuda_bf16.h>
#include <cstdint>

// Problem constants
#define M_ROWS 4096
#define K_DIM  256
#define NN     16384
#define KTOP   1638

// GEMM tiling (R13 structure: 512 threads, full K, 1 CTA/SM) — measured ~515us
#define TR 128
#define TC 128
#define GEMM_THREADS 512
#define SLOTS 64                     // per-column CSC capacity (max nnz ~48)
#define NQ (SLOTS / 2)               // 32 quads (2 pairs each)
#define XS_STRIDE 132                // 132*4=528=33*16 -> LDS.128 16B-aligned
#define OS_STRIDE 129                // conflict-free column stores

#define PP_OFF   (K_DIM * XS_STRIDE)            // 33792 floats; *4 % 16 == 0
#define SCNT_OFF (PP_OFF + NQ * TC * 4)         // + 16384 floats (64 KB quads)
#define GEMM_SMEM ((SCNT_OFF + TC) * 4)         // 201216 B -> 1 CTA/SM

// ---------------------------------------------------------------------------
// Scratch: quad-packed CSC of W, [quad][n] layout (coalesced everywhere).
// quad = (w0, k0-as-float-bits, w1, k1-as-float-bits). Tail zeroed => inert.
// ---------------------------------------------------------------------------
__device__ float4 g_pairQ[(size_t)NQ * NN];      // 8.4 MB
__device__ int    g_cnt[NN];

// ---------------------------------------------------------------------------
// Kernel 1: build quad CSC (+ inline tail zero-fill). One thread per column;
// W reads and g_pairQ writes both coalesced across adjacent n. unroll 4 for
// load MLP (kernel is latency-bound at 16K threads).
// ---------------------------------------------------------------------------
__global__ void __launch_bounds__(128) build_pack_kernel(const float* __restrict__ W) {
    const int n = blockIdx.x * blockDim.x + threadIdx.x;
    if (n >= NN) return;
    float4 quad = make_float4(0.f, 0.f, 0.f, 0.f);
    int c = 0;
#pragma unroll 4
    for (int k = 0; k < K_DIM; ++k) {
        const float w = W[(size_t)k * NN + n];
        if (w != 0.0f && c < SLOTS) {
            if ((c & 1) == 0) { quad.x = w; quad.y = __int_as_float(k); }
            else {
                quad.z = w; quad.w = __int_as_float(k);
                g_pairQ[(size_t)(c >> 1) * NN + n] = quad;
                quad = make_float4(0.f, 0.f, 0.f, 0.f);
            }
            ++c;
        }
    }
    int q = c >> 1;
    if (c & 1) { g_pairQ[(size_t)q * NN + n] = quad; ++q; }
    for (; q < NQ; ++q)
        g_pairQ[(size_t)q * NN + n] = make_float4(0.f, 0.f, 0.f, 0.f);
    g_cnt[n] = c;
}

// ---------------------------------------------------------------------------
// Kernel 2: sparse GEMM  out = relu(x @ W + bias), dense output. (R13, exact)
// 512 threads / 16 warps; warp owns 8 columns, lane owns 4 consecutive rows
// (float4 from smem x-tile). Quad lists staged in SMEM; in-loop reads are
// warp-uniform LDS.128 broadcasts carrying TWO (w,k) pairs each.
// ---------------------------------------------------------------------------
__global__ void __launch_bounds__(GEMM_THREADS, 1) gemm_kernel(
    const float* __restrict__ x,
    const float* __restrict__ bias,
    float* __restrict__ out)
{
    extern __shared__ float sm[];
    float*  xs  = sm;                            // [K_DIM][XS_STRIDE]
    float4* ppq = (float4*)(sm + PP_OFF);        // [NQ][TC]
    int*    scnt = (int*)(sm + SCNT_OFF);        // [TC] padded counts

    const int row0 = blockIdx.y * TR;
    const int col0 = blockIdx.x * TC;
    const int tid  = threadIdx.x;

    // fill x tile transposed: xs[k][r]  (gmem coalesced)
    for (int u = tid; u < TR * K_DIM; u += GEMM_THREADS) {
        const int r = u >> 8;                // 0..127
        const int k = u & 255;               // 0..255
        xs[k * XS_STRIDE + r] = x[(size_t)(row0 + r) * K_DIM + k];
    }
    // fill quad tile: ppq[q][c] <- g_pairQ[q][col0+c]  (LDG.128 coalesced)
    for (int u = tid; u < NQ * TC; u += GEMM_THREADS) {
        const int q = u >> 7;
        const int c = u & 127;
        ppq[q * TC + c] = g_pairQ[(size_t)q * NN + col0 + c];
    }
    if (tid < TC) scnt[tid] = (g_cnt[col0 + tid] + 7) & ~7;   // pad to 8
    __syncthreads();

    const int warp  = tid >> 5;              // 0..15
    const int lane  = tid & 31;
    const int rbase = lane << 2;

    float4 acc[8];
#pragma unroll
    for (int cc = 0; cc < 8; ++cc) {
        const int c = (warp << 3) + cc;
        const int cntp = scnt[c];
        const float4* pq = ppq + c;
        float4 a = make_float4(0.f, 0.f, 0.f, 0.f);
        for (int j = 0; j < cntp; j += 8) {  // tail slots zero => inert
            const int sp = j >> 1;
            const float4 q0 = pq[(sp + 0) * TC];
            const float4 q1 = pq[(sp + 1) * TC];
            const float4 q2 = pq[(sp + 2) * TC];
            const float4 q3 = pq[(sp + 3) * TC];
            {
                const float4 xv = *(const float4*)(xs + __float_as_int(q0.y) * XS_STRIDE + rbase);
                a.x = fmaf(xv.x, q0.x, a.x); a.y = fmaf(xv.y, q0.x, a.y);
                a.z = fmaf(xv.z, q0.x, a.z); a.w = fmaf(xv.w, q0.x, a.w);
            }
            {
                const float4 xv = *(const float4*)(xs + __float_as_int(q0.w) * XS_STRIDE + rbase);
                a.x = fmaf(xv.x, q0.z, a.x); a.y = fmaf(xv.y, q0.z, a.y);
                a.z = fmaf(xv.z, q0.z, a.z); a.w = fmaf(xv.w, q0.z, a.w);
            }
            {
                const float4 xv = *(const float4*)(xs + __float_as_int(q1.y) * XS_STRIDE + rbase);
                a.x = fmaf(xv.x, q1.x, a.x); a.y = fmaf(xv.y, q1.x, a.y);
                a.z = fmaf(xv.z, q1.x, a.z); a.w = fmaf(xv.w, q1.x, a.w);
            }
            {
                const float4 xv = *(const float4*)(xs + __float_as_int(q1.w) * XS_STRIDE + rbase);
                a.x = fmaf(xv.x, q1.z, a.x); a.y = fmaf(xv.y, q1.z, a.y);
                a.z = fmaf(xv.z, q1.z, a.z); a.w = fmaf(xv.w, q1.z, a.w);
            }
            {
                const float4 xv = *(const float4*)(xs + __float_as_int(q2.y) * XS_STRIDE + rbase);
                a.x = fmaf(xv.x, q2.x, a.x); a.y = fmaf(xv.y, q2.x, a.y);
                a.z = fmaf(xv.z, q2.x, a.z); a.w = fmaf(xv.w, q2.x, a.w);
            }
            {
                const float4 xv = *(const float4*)(xs + __float_as_int(q2.w) * XS_STRIDE + rbase);
                a.x = fmaf(xv.x, q2.z, a.x); a.y = fmaf(xv.y, q2.z, a.y);
                a.z = fmaf(xv.z, q2.z, a.z); a.w = fmaf(xv.w, q2.z, a.w);
            }
            {
                const float4 xv = *(const float4*)(xs + __float_as_int(q3.y) * XS_STRIDE + rbase);
                a.x = fmaf(xv.x, q3.x, a.x); a.y = fmaf(xv.y, q3.x, a.y);
                a.z = fmaf(xv.z, q3.x, a.z); a.w = fmaf(xv.w, q3.x, a.w);
            }
            {
                const float4 xv = *(const float4*)(xs + __float_as_int(q3.w) * XS_STRIDE + rbase);
                a.x = fmaf(xv.x, q3.z, a.x); a.y = fmaf(xv.y, q3.z, a.y);
                a.z = fmaf(xv.z, q3.z, a.z); a.w = fmaf(xv.w, q3.z, a.w);
            }
        }
        const float b = __ldg(bias + col0 + c);
        a.x = fmaxf(a.x + b, 0.f);
        a.y = fmaxf(a.y + b, 0.f);
        a.z = fmaxf(a.z + b, 0.f);
        a.w = fmaxf(a.w + b, 0.f);
        acc[cc] = a;
    }
    __syncthreads();                         // xs/ppq reads done -> reuse

    float* os = sm;                          // [TR][OS_STRIDE], overlays xs
#pragma unroll
    for (int cc = 0; cc < 8; ++cc) {
        const int c = (warp << 3) + cc;
        os[(rbase + 0) * OS_STRIDE + c] = acc[cc].x;
        os[(rbase + 1) * OS_STRIDE + c] = acc[cc].y;
        os[(rbase + 2) * OS_STRIDE + c] = acc[cc].z;
        os[(rbase + 3) * OS_STRIDE + c] = acc[cc].w;
    }
    __syncthreads();

    // flush tile, scalar + coalesced (consecutive threads -> consecutive cols)
    for (int l = tid; l < TR * TC; l += GEMM_THREADS) {
        const int r = l >> 7;
        const int c = l & 127;
        out[(size_t)(row0 + r) * NN + col0 + c] = os[r * OS_STRIDE + c];
    }
}

// ---------------------------------------------------------------------------
// Kernel 3: per-row EXACT top-K in 2 reads + 1 write (input is exact fp32).
// Pass1: 12-bit histogram (bits[31:20]) -> threshold bin b1 + krem.
// Pass2 (fused): keep bins > b1 as-is; compact bin-b1 elements (value,index)
// into smem and zero them; zero bins < b1. Then rank candidates exactly
// (lowest-index ties, = lax.top_k) and scatter the krem kept ones back.
// bin population known from hist[b1] BEFORE pass2 -> safe fallback path.
// relu => all >= 0 => uint compare is order-preserving.
// ---------------------------------------------------------------------------
#define CAP 1024

__global__ void __launch_bounds__(256) topk_kernel(float* __restrict__ out) {
    __shared__ int hist[4096];
    __shared__ unsigned int candv[CAP];
    __shared__ int candi[CAP];
    __shared__ int chunksum[256];
    __shared__ int s_b1, s_krem, s_cnt;

    const int t = threadIdx.x;
    const int lane = t & 31;
    float* rp = out + (size_t)blockIdx.x * NN;
    const uint4* rp4 = (const uint4*)rp;

    for (int i = t; i < 4096; i += 256) hist[i] = 0;
    if (t == 0) s_cnt = 0;
    __syncthreads();

    // ---- pass 1: 12-bit histogram (zeros counted without atomics) ----
    {
        int zc = 0;
        for (int i = t; i < NN / 4; i += 256) {
            const uint4 q = rp4[i];
            if (q.x) atomicAdd(&hist[q.x >> 20], 1); else ++zc;
            if (q.y) atomicAdd(&hist[q.y >> 20], 1); else ++zc;
            if (q.z) atomicAdd(&hist[q.z >> 20], 1); else ++zc;
            if (q.w) atomicAdd(&hist[q.w >> 20], 1); else ++zc;
        }
#pragma unroll
        for (int off = 16; off; off >>= 1) zc += __shfl_down_sync(0xffffffffu, zc, off);
        if (lane == 0 && zc) atomicAdd(&hist[0], zc);
    }
    __syncthreads();
    { int s = 0; for (int k = 0; k < 16; ++k) s += hist[t * 16 + k]; chunksum[t] = s; }
    __syncthreads();
    if (t == 0) {
        int kr = KTOP, c = 255;
        for (;; --c) { const int h = chunksum[c]; if (h >= kr) break; kr -= h; }
        int b = c * 16 + 15;
        for (;; --b) { const int h = hist[b]; if (h >= kr) break; kr -= h; }
        s_b1 = b; s_krem = kr;
    }
    __syncthreads();
    const int b1 = s_b1;
    const int krem = s_krem;
    const int binpop = hist[b1];          // population of the threshold bin

    // b1 == 0: all positives kept, zeros stay zero -> row already correct
    if (b1 == 0) return;

    uint4* wp4 = (uint4*)rp;

    if (binpop > CAP) {
        // ~impossible fallback (needs >1024 near-ties in one bin): keep the
        // whole threshold bin, zero only strictly-lower bins.
        for (int i = t; i < NN / 4; i += 256) {
            uint4 q = rp4[i];
            unsigned int* pc = (unsigned int*)&q;
#pragma unroll
            for (int c2 = 0; c2 < 4; ++c2)
                if ((int)(pc[c2] >> 20) < b1) pc[c2] = 0u;
            wp4[i] = q;
        }
        return;
    }

    // ---- pass 2 (fused): compact bin-b1 candidates + masked write-back ----
    for (int i = t; i < NN / 4; i += 256) {
        uint4 q = rp4[i];
        const int base = i * 4;
        unsigned int* pc = (unsigned int*)&q;
#pragma unroll
        for (int c2 = 0; c2 < 4; ++c2) {
            const int bin = (int)(pc[c2] >> 20);
            if (bin == b1) {
                const int p = atomicAdd(&s_cnt, 1);
                candv[p] = pc[c2]; candi[p] = base + c2;
                pc[c2] = 0u;                  // scatter restores the kept ones
            } else if (bin < b1) {
                pc[c2] = 0u;
            }
        }
        wp4[i] = q;
    }
    __syncthreads();
    const int cnt = s_cnt;                    // == binpop <= CAP

    // ---- exact ranking among candidates, lowest-index ties first ----
    // values are the EXACT fp32 h values (no recompute needed).
    for (int i = t; i < cnt; i += 256) {
        const unsigned int u = candv[i];
        const int idx = candi[i];
        int r = 0;
        for (int j = 0; j < cnt; ++j) {
            const unsigned int v = candv[j];
            r += (v > u) || (v == u && candi[j] < idx);
        }
        if (r >= krem) candi[i] = -1;         // mark dropped
    }
    __syncthreads();

    // ---- scatter kept candidates back (exact values) ----
    for (int i = t; i < cnt; i += 256) {
        const int idx = candi[i];
        if (idx >= 0) rp[idx] = __uint_as_float(candv[i]);
    }
}

// ---------------------------------------------------------------------------
// Launch
// ---------------------------------------------------------------------------
extern "C" void kernel_launch(void* const* d_in, const int* in_sizes, int n_in,
                              void* d_out, int out_size)
{
    const float* x = nullptr;
    const float* W = nullptr;
    const float* bias = nullptr;
    for (int i = 0; i < n_in; ++i) {
        if (in_sizes[i] == M_ROWS * K_DIM)      x = (const float*)d_in[i];
        else if (in_sizes[i] == K_DIM * NN)     W = (const float*)d_in[i];
        else if (in_sizes[i] == NN)             bias = (const float*)d_in[i];
    }
    float* out = (float*)d_out;

    cudaFuncSetAttribute(gemm_kernel, cudaFuncAttributeMaxDynamicSharedMemorySize, GEMM_SMEM);

    build_pack_kernel<<<NN / 128, 128>>>(W);

    dim3 ggrid(NN / TC, M_ROWS / TR);        // 128 x 32 = 4096 tiles
    gemm_kernel<<<ggrid, GEMM_THREADS, GEMM_SMEM>>>(x, bias, out);

    topk_kernel<<<M_ROWS, 256>>>(out);
}